// round 3
// baseline (speedup 1.0000x reference)
#include <cuda_runtime.h>

#define N_NODES 100000
#define N_EDGES 1600000
#define F_IN 16
#define F_MID 32

#define SCAN_T 256
#define ELEMS_PER_BLOCK 1024
#define N_SCAN_BLOCKS ((N_NODES + ELEMS_PER_BLOCK - 1) / ELEMS_PER_BLOCK)  // 98
#define N_PAD (N_SCAN_BLOCKS * ELEMS_PER_BLOCK)                            // 100352

// Scratch (device globals). Padded regions are never written -> stay zero.
__device__ int   g_cnt[N_PAD];
__device__ int   g_loc[N_PAD];
__device__ int   g_rp [N_NODES];
__device__ int   g_part[N_SCAN_BLOCKS];
__device__ int   g_pos[N_EDGES];
__device__ int   g_csr[N_EDGES];
__device__ float g_dis[N_NODES];
__device__ __align__(16) float g_xs [N_NODES * F_IN];
__device__ __align__(16) float g_AX [N_NODES * F_IN];
__device__ __align__(16) float g_h2s[N_NODES * 2];

// 1) zero the histogram
__global__ void k_zero() {
    int v = blockIdx.x * blockDim.x + threadIdx.x;
    if (v < N_NODES) g_cnt[v] = 0;
}

// 2) histogram + per-edge slot in ONE atomic pass (4 edges/thread)
__global__ void k_hist_pos(const int* __restrict__ ei) {
    int t = blockIdx.x * blockDim.x + threadIdx.x;
    long e = (long)t * 4;
    if (e >= N_EDGES) return;
    int4 d4 = *(const int4*)(ei + N_EDGES + e);
    int4 p4;
    p4.x = atomicAdd(&g_cnt[d4.x], 1);
    p4.y = atomicAdd(&g_cnt[d4.y], 1);
    p4.z = atomicAdd(&g_cnt[d4.z], 1);
    p4.w = atomicAdd(&g_cnt[d4.w], 1);
    *(int4*)(g_pos + e) = p4;
}

// 3a) block-local exclusive scan (1024 elems/block, 4/thread)
__global__ void k_scan_part() {
    __shared__ int sdata[SCAN_T];
    int t = threadIdx.x;
    long base = (long)blockIdx.x * ELEMS_PER_BLOCK + (long)t * 4;
    int4 c4 = *(const int4*)(g_cnt + base);
    int s = c4.x + c4.y + c4.z + c4.w;
    sdata[t] = s;
    __syncthreads();
    int incl = s;
#pragma unroll
    for (int off = 1; off < SCAN_T; off <<= 1) {
        int v = (t >= off) ? sdata[t - off] : 0;
        __syncthreads();
        incl += v;
        sdata[t] = incl;
        __syncthreads();
    }
    int excl = incl - s;
    int4 o4;
    o4.x = excl;
    o4.y = excl + c4.x;
    o4.z = o4.y + c4.y;
    o4.w = o4.z + c4.z;
    *(int4*)(g_loc + base) = o4;
    if (t == SCAN_T - 1) g_part[blockIdx.x] = incl;
}

// 3b) exclusive scan of the 98 block partials (single block)
__global__ void k_scan_top() {
    __shared__ int sp[N_SCAN_BLOCKS];
    int t = threadIdx.x;
    if (t < N_SCAN_BLOCKS) sp[t] = g_part[t];
    __syncthreads();
    if (t == 0) {
        int run = 0;
        for (int i = 0; i < N_SCAN_BLOCKS; i++) { int v = sp[i]; sp[i] = run; run += v; }
    }
    __syncthreads();
    if (t < N_SCAN_BLOCKS) g_part[t] = sp[t];
}

// 3c) row_ptr = local + block offset; dis = rsqrt(deg+1)
__global__ void k_scan_add() {
    int v = blockIdx.x * blockDim.x + threadIdx.x;
    if (v >= N_NODES) return;
    g_rp[v]  = g_loc[v] + g_part[v >> 10];
    g_dis[v] = rsqrtf((float)(g_cnt[v] + 1));
}

// 4) scatter edges into CSR (no atomics): csr[rp[dst]+pos[e]] = src
__global__ void k_scatter(const int* __restrict__ ei) {
    int t = blockIdx.x * blockDim.x + threadIdx.x;
    long e = (long)t * 4;
    if (e >= N_EDGES) return;
    int4 s4 = *(const int4*)(ei + e);
    int4 d4 = *(const int4*)(ei + N_EDGES + e);
    int4 p4 = *(const int4*)(g_pos + e);
    g_csr[g_rp[d4.x] + p4.x] = s4.x;
    g_csr[g_rp[d4.y] + p4.y] = s4.y;
    g_csr[g_rp[d4.z] + p4.z] = s4.z;
    g_csr[g_rp[d4.w] + p4.w] = s4.w;
}

// 5) xs = dis * x  (4 lanes per node)
__global__ void k_pre(const float* __restrict__ x) {
    long idx = (long)blockIdx.x * blockDim.x + threadIdx.x;
    if (idx >= (long)N_NODES * 4) return;
    int v = (int)(idx >> 2);
    int q = (int)(idx & 3);
    float dis = g_dis[v];
    float4 xv = *(const float4*)(x + (long)v * F_IN + q * 4);
    xv.x *= dis; xv.y *= dis; xv.z *= dis; xv.w *= dis;
    *(float4*)(g_xs + (long)v * F_IN + q * 4) = xv;
}

// 6) layer-1 aggregation: warp per node, 8 edge-slots x 4 lanes, NO atomics
__global__ void k_agg1() {
    long gtid = (long)blockIdx.x * blockDim.x + threadIdx.x;
    int v = (int)(gtid >> 5);
    if (v >= N_NODES) return;
    int lane = threadIdx.x & 31;
    int slot = lane >> 2;
    int q    = lane & 3;
    int start = g_rp[v];
    int d     = g_cnt[v];
    float4 acc = make_float4(0.f, 0.f, 0.f, 0.f);
    for (int i = slot; i < d; i += 8) {
        int s = g_csr[start + i];
        float4 w = *(const float4*)(g_xs + (long)s * F_IN + q * 4);
        acc.x += w.x; acc.y += w.y; acc.z += w.z; acc.w += w.w;
    }
    __syncwarp();
#pragma unroll
    for (int m = 16; m >= 4; m >>= 1) {
        acc.x += __shfl_xor_sync(0xffffffffu, acc.x, m);
        acc.y += __shfl_xor_sync(0xffffffffu, acc.y, m);
        acc.z += __shfl_xor_sync(0xffffffffu, acc.z, m);
        acc.w += __shfl_xor_sync(0xffffffffu, acc.w, m);
    }
    if (lane < 4) {  // q == lane
        float4 self = *(const float4*)(g_xs + (long)v * F_IN + lane * 4);
        acc.x += self.x; acc.y += self.y; acc.z += self.z; acc.w += self.w;
        *(float4*)(g_AX + (long)v * F_IN + lane * 4) = acc;
    }
}

// 7) fused epilogue: h2s = dis * (relu(dis*(AX@W1)+b1) @ W2)
__global__ void k_layer2(const float* __restrict__ W1, const float* __restrict__ b1,
                         const float* __restrict__ W2) {
    __shared__ float sW1[F_IN * F_MID];
    __shared__ float sb1[F_MID];
    __shared__ float sW2[F_MID * 2];
    int t = threadIdx.x;
    for (int i = t; i < F_IN * F_MID; i += blockDim.x) sW1[i] = W1[i];
    if (t < F_MID) sb1[t] = b1[t];
    if (t < F_MID * 2) sW2[t] = W2[t];
    __syncthreads();
    int v = blockIdx.x * blockDim.x + t;
    if (v >= N_NODES) return;
    float dis = g_dis[v];

    float ax[F_IN];
    const float4* Ar = (const float4*)(g_AX + (long)v * F_IN);
#pragma unroll
    for (int q = 0; q < 4; q++) {
        float4 a4 = Ar[q];
        ax[q * 4 + 0] = a4.x; ax[q * 4 + 1] = a4.y;
        ax[q * 4 + 2] = a4.z; ax[q * 4 + 3] = a4.w;
    }
    float h[F_MID];
#pragma unroll
    for (int j = 0; j < F_MID; j++) h[j] = 0.0f;
#pragma unroll
    for (int k = 0; k < F_IN; k++) {
        float a = ax[k];
#pragma unroll
        for (int j = 0; j < F_MID; j++) h[j] = fmaf(a, sW1[k * F_MID + j], h[j]);
    }
    float acc0 = 0.f, acc1 = 0.f;
#pragma unroll
    for (int j = 0; j < F_MID; j++) {
        float hj = fmaxf(fmaf(dis, h[j], sb1[j]), 0.0f);
        acc0 = fmaf(hj, sW2[j * 2 + 0], acc0);
        acc1 = fmaf(hj, sW2[j * 2 + 1], acc1);
    }
    *(float2*)(g_h2s + (long)v * 2) = make_float2(dis * acc0, dis * acc1);
}

// 8) layer-2 aggregation + final scale/bias, fused: warp per node, 16 slots x 2 lanes
__global__ void k_agg2_out(const float* __restrict__ b2, float* __restrict__ out) {
    long gtid = (long)blockIdx.x * blockDim.x + threadIdx.x;
    int v = (int)(gtid >> 5);
    if (v >= N_NODES) return;
    int lane = threadIdx.x & 31;
    int slot = lane >> 1;
    int c    = lane & 1;
    int start = g_rp[v];
    int d     = g_cnt[v];
    float acc = 0.0f;
    for (int i = slot; i < d; i += 16) {
        int s = g_csr[start + i];
        acc += g_h2s[(long)s * 2 + c];
    }
    __syncwarp();
#pragma unroll
    for (int m = 16; m >= 2; m >>= 1)
        acc += __shfl_xor_sync(0xffffffffu, acc, m);
    if (lane < 2) {  // c == lane
        float self = g_h2s[(long)v * 2 + lane];
        out[(long)v * 2 + lane] = fmaf(g_dis[v], acc + self, b2[lane]);
    }
}

extern "C" void kernel_launch(void* const* d_in, const int* in_sizes, int n_in,
                              void* d_out, int out_size) {
    const float* x  = (const float*)d_in[0];
    const int*   ei = (const int*)  d_in[1];
    const float* W1 = (const float*)d_in[2];
    const float* b1 = (const float*)d_in[3];
    const float* W2 = (const float*)d_in[4];
    const float* b2 = (const float*)d_in[5];
    float* out = (float*)d_out;

    const int T = 256;
    k_zero<<<(N_NODES + T - 1) / T, T>>>();
    k_hist_pos<<<(N_EDGES / 4 + T - 1) / T, T>>>(ei);
    k_scan_part<<<N_SCAN_BLOCKS, SCAN_T>>>();
    k_scan_top<<<1, 128>>>();
    k_scan_add<<<(N_NODES + T - 1) / T, T>>>();
    k_scatter<<<(N_EDGES / 4 + T - 1) / T, T>>>(ei);
    k_pre<<<((N_NODES * 4) + T - 1) / T, T>>>(x);
    {
        long n = (long)N_NODES * 32;
        k_agg1<<<(unsigned)((n + T - 1) / T), T>>>();
    }
    k_layer2<<<(N_NODES + T - 1) / T, T>>>(W1, b1, W2);
    {
        long n = (long)N_NODES * 32;
        k_agg2_out<<<(unsigned)((n + T - 1) / T), T>>>(b2, out);
    }
}